// round 1
// baseline (speedup 1.0000x reference)
#include <cuda_runtime.h>

#define N_ATOMS 8000
#define N_PAIRS 80000
#define NF 32
#define N_DIST 16
#define GN_EPS 1e-5f
#define HARD_CUT 6.5f

// Scratch: A[a][d][o] = sum_f feat[a,f] * W[d,o,f]   (16.4 MB, fits L2)
__device__ float g_A[N_ATOMS * N_DIST * NF];

__global__ void k1_precompute(const float* __restrict__ feat,
                              const float* __restrict__ W) {
    int idx = blockIdx.x * blockDim.x + threadIdx.x;
    if (idx >= N_ATOMS * N_DIST * NF) return;
    int a = idx >> 9;          // 512 entries per atom
    int e = idx & 511;
    int d = e >> 5;
    int o = e & 31;
    const float* frow = feat + a * NF;          // broadcast within warp
    const float* wrow = W + (d * NF + o) * NF;  // contiguous 128B row -> LDG.128
    float acc = 0.f;
#pragma unroll
    for (int f = 0; f < NF; f++) acc += frow[f] * wrow[f];
    g_A[idx] = acc;
}

__global__ void __launch_bounds__(256)
k2_atoms(const float* __restrict__ feat,
         const float* __restrict__ rhats,
         const float* __restrict__ dist,
         const float* __restrict__ selfW,
         const float* __restrict__ selfB,
         const float* __restrict__ mixW,
         const float* __restrict__ gnw,
         const float* __restrict__ gnb,
         const float* __restrict__ mu,
         const float* __restrict__ sigma,
         const int* __restrict__ pf,
         const int* __restrict__ ps,
         float* __restrict__ out) {
    const unsigned FULL = 0xffffffffu;
    int warp = (blockIdx.x * blockDim.x + threadIdx.x) >> 5;
    int lane = threadIdx.x & 31;
    if (warp >= N_ATOMS) return;
    const int a = warp;

    // Segment bounds via binary search (pair_first is sorted; uniform per warp)
    int lo = 0, hi = N_PAIRS;
    while (lo < hi) { int m = (lo + hi) >> 1; if (pf[m] < a) lo = m + 1; else hi = m; }
    const int segs = lo;
    hi = N_PAIRS;
    while (lo < hi) { int m = (lo + hi) >> 1; if (pf[m] < a + 1) lo = m + 1; else hi = m; }
    const int sege = lo;

    float myMu = 0.f, mySig = 1.f;
    if (lane < N_DIST) { myMu = mu[lane]; mySig = sigma[lane]; }

    float tf0 = 0.f, tf1 = 0.f, tf2 = 0.f, tf3 = 0.f;

    for (int p = segs; p < sege; p++) {
        int   j  = ps[p];
        float dd = dist[p];
        float4 r = *reinterpret_cast<const float4*>(rhats + 4 * p);

        // sensitivity: lane d < 16 computes sense_d
        float sv = 0.f;
        if (lane < N_DIST) {
            float z   = (1.f / dd - myMu) / mySig;
            float c   = __cosf(dd * (float)(3.14159265358979323846 / (2.0 * 6.5)));
            float cut = (dd < HARD_CUT) ? c * c : 0.f;
            sv = __expf(-0.5f * z * z) * cut;
        }

        // gather A[j, :, lane] — 16 independent coalesced loads (MLP)
        const float* Aj = g_A + j * (N_DIST * NF);
        float av[N_DIST];
#pragma unroll
        for (int d = 0; d < N_DIST; d++) av[d] = Aj[d * NF + lane];

        float v = 0.f;
#pragma unroll
        for (int d = 0; d < N_DIST; d++)
            v += __shfl_sync(FULL, sv, d) * av[d];

        tf0 += r.x * v; tf1 += r.y * v; tf2 += r.z * v; tf3 += r.w * v;
    }

    // invariants: x0 = l=0 scalar, x1 = |l=1 vector|^2
    float x0 = tf0;
    float x1 = tf1 * tf1 + tf2 * tf2 + tf3 * tf3;

    // GroupNorm: each group == the 32 lanes of this warp (two-pass for stability)
    float s0 = x0, s1 = x1;
#pragma unroll
    for (int off = 16; off; off >>= 1) {
        s0 += __shfl_xor_sync(FULL, s0, off);
        s1 += __shfl_xor_sync(FULL, s1, off);
    }
    float m0 = s0 * (1.f / 32.f), m1 = s1 * (1.f / 32.f);
    float d0 = x0 - m0, d1 = x1 - m1;
    float q0 = d0 * d0, q1 = d1 * d1;
#pragma unroll
    for (int off = 16; off; off >>= 1) {
        q0 += __shfl_xor_sync(FULL, q0, off);
        q1 += __shfl_xor_sync(FULL, q1, off);
    }
    float var0 = q0 * (1.f / 32.f), var1 = q1 * (1.f / 32.f);
    float xn0 = d0 * rsqrtf(var0 + GN_EPS) * gnw[lane]      + gnb[lane];
    float xn1 = d1 * rsqrtf(var1 + GN_EPS) * gnw[32 + lane] + gnb[32 + lane];

    // mixing: out[o2] = sum_o xn0(o)*Mw[(2o)*32+o2] + xn1(o)*Mw[(2o+1)*32+o2]
    float acc = 0.f;
#pragma unroll
    for (int o = 0; o < 32; o++) {
        float a0 = __shfl_sync(FULL, xn0, o);
        float a1 = __shfl_sync(FULL, xn1, o);
        acc += a0 * mixW[(o * 2 + 0) * 32 + lane]
             + a1 * mixW[(o * 2 + 1) * 32 + lane];
    }

    // self interaction: sp[o] = b[o] + sum_f feat[a,f] * selfW[o,f]
    const float* frow = feat + a * NF;
    const float* wrow = selfW + lane * NF;
    float sp = selfB[lane];
#pragma unroll
    for (int f = 0; f < NF; f++) sp += frow[f] * wrow[f];

    out[a * NF + lane] = acc + sp;
}

extern "C" void kernel_launch(void* const* d_in, const int* in_sizes, int n_in,
                              void* d_out, int out_size) {
    const float* in_features = (const float*)d_in[0];
    const float* tensor_rhats = (const float*)d_in[1];
    const float* dist_pairs   = (const float*)d_in[2];
    const float* int_weights  = (const float*)d_in[3];
    const float* selfint_w    = (const float*)d_in[4];
    const float* selfint_b    = (const float*)d_in[5];
    const float* mixing_w     = (const float*)d_in[6];
    const float* gn_weight    = (const float*)d_in[7];
    const float* gn_bias      = (const float*)d_in[8];
    const float* sens_mu      = (const float*)d_in[9];
    const float* sens_sigma   = (const float*)d_in[10];
    const int*   pair_first   = (const int*)d_in[11];
    const int*   pair_second  = (const int*)d_in[12];
    float* out = (float*)d_out;

    {
        int total = N_ATOMS * N_DIST * NF;
        int threads = 256;
        int blocks = (total + threads - 1) / threads;
        k1_precompute<<<blocks, threads>>>(in_features, int_weights);
    }
    {
        int threads = 256;                 // 8 warps/block, 1 warp per atom
        int blocks = (N_ATOMS * 32 + threads - 1) / threads;
        k2_atoms<<<blocks, threads>>>(in_features, tensor_rhats, dist_pairs,
                                      selfint_w, selfint_b, mixing_w,
                                      gn_weight, gn_bias, sens_mu, sens_sigma,
                                      pair_first, pair_second, out);
    }
}

// round 3
// speedup vs baseline: 5.6547x; 5.6547x over previous
#include <cuda_runtime.h>

#define N_ATOMS 8000
#define N_PAIRS 80000
#define NF 32
#define N_DIST 16
#define S (N_DIST * NF)          // 512
#define GN_EPS 1e-5f
#define HARD_CUT 6.5f

// Scratch: A[a][d][o] = sum_f feat[a,f] * W[d,o,f]   (16.4 MB, fits L2)
__device__ float g_A[N_ATOMS * S];
// Transposed weights: Wt[f][d*32+o] = W[d][o][f]  (64 KB, lives in L1)
__device__ float g_Wt[NF * S];

__global__ void k0_transpose(const float* __restrict__ W) {
    int idx = blockIdx.x * blockDim.x + threadIdx.x;   // over S*NF = 16384
    if (idx >= S * NF) return;
    int e = idx >> 5;      // d*32+o
    int f = idx & 31;
    g_Wt[f * S + e] = W[e * NF + f];
}

// One thread -> 4 consecutive outputs of A[a, :]; fully coalesced float4 loads.
__global__ void __launch_bounds__(256)
k1_precompute(const float* __restrict__ feat) {
    int idx = blockIdx.x * blockDim.x + threadIdx.x;   // over N_ATOMS * 128
    if (idx >= N_ATOMS * (S / 4)) return;
    int a  = idx >> 7;           // 128 float4 per atom
    int e4 = idx & 127;
    const float4* frow4 = reinterpret_cast<const float4*>(feat + a * NF);
    const float4* Wt4   = reinterpret_cast<const float4*>(g_Wt);
    float4 acc = make_float4(0.f, 0.f, 0.f, 0.f);
#pragma unroll
    for (int f4 = 0; f4 < NF / 4; f4++) {
        float4 fr = frow4[f4];
        float4 w0 = Wt4[(4 * f4 + 0) * (S / 4) + e4];
        float4 w1 = Wt4[(4 * f4 + 1) * (S / 4) + e4];
        float4 w2 = Wt4[(4 * f4 + 2) * (S / 4) + e4];
        float4 w3 = Wt4[(4 * f4 + 3) * (S / 4) + e4];
        acc.x += fr.x * w0.x + fr.y * w1.x + fr.z * w2.x + fr.w * w3.x;
        acc.y += fr.x * w0.y + fr.y * w1.y + fr.z * w2.y + fr.w * w3.y;
        acc.z += fr.x * w0.z + fr.y * w1.z + fr.z * w2.z + fr.w * w3.z;
        acc.w += fr.x * w0.w + fr.y * w1.w + fr.z * w2.w + fr.w * w3.w;
    }
    reinterpret_cast<float4*>(g_A)[idx] = acc;
}

__global__ void __launch_bounds__(256)
k2_atoms(const float* __restrict__ feat,
         const float* __restrict__ rhats,
         const float* __restrict__ dist,
         const float* __restrict__ selfW,
         const float* __restrict__ selfB,
         const float* __restrict__ mixW,
         const float* __restrict__ gnw,
         const float* __restrict__ gnb,
         const float* __restrict__ mu,
         const float* __restrict__ sigma,
         const int* __restrict__ pf,
         const int* __restrict__ ps,
         float* __restrict__ out) {
    const unsigned FULL = 0xffffffffu;
    int warp = (blockIdx.x * blockDim.x + threadIdx.x) >> 5;
    int lane = threadIdx.x & 31;
    if (warp >= N_ATOMS) return;
    const int a = warp;

    // Segment bounds via binary search (pair_first is sorted; uniform per warp)
    int lo = 0, hi = N_PAIRS;
    while (lo < hi) { int m = (lo + hi) >> 1; if (pf[m] < a) lo = m + 1; else hi = m; }
    const int segs = lo;
    hi = N_PAIRS;
    while (lo < hi) { int m = (lo + hi) >> 1; if (pf[m] < a + 1) lo = m + 1; else hi = m; }
    const int sege = lo;

    float myMu = 0.f, mySig = 1.f;
    if (lane < N_DIST) { myMu = mu[lane]; mySig = sigma[lane]; }

    float tf0 = 0.f, tf1 = 0.f, tf2 = 0.f, tf3 = 0.f;

    for (int p = segs; p < sege; p++) {
        int   j  = ps[p];
        float dd = dist[p];
        float4 r = *reinterpret_cast<const float4*>(rhats + 4 * p);

        // sensitivity: lane d < 16 computes sense_d
        float sv = 0.f;
        if (lane < N_DIST) {
            float z   = (1.f / dd - myMu) / mySig;
            float c   = __cosf(dd * (float)(3.14159265358979323846 / (2.0 * 6.5)));
            float cut = (dd < HARD_CUT) ? c * c : 0.f;
            sv = __expf(-0.5f * z * z) * cut;
        }

        // gather A[j, :, lane] — 16 independent coalesced loads (MLP)
        const float* Aj = g_A + j * S;
        float av[N_DIST];
#pragma unroll
        for (int d = 0; d < N_DIST; d++) av[d] = Aj[d * NF + lane];

        float v = 0.f;
#pragma unroll
        for (int d = 0; d < N_DIST; d++)
            v += __shfl_sync(FULL, sv, d) * av[d];

        tf0 += r.x * v; tf1 += r.y * v; tf2 += r.z * v; tf3 += r.w * v;
    }

    // invariants: x0 = l=0 scalar, x1 = |l=1 vector|^2
    float x0 = tf0;
    float x1 = tf1 * tf1 + tf2 * tf2 + tf3 * tf3;

    // GroupNorm: each group == the 32 lanes of this warp
    float s0 = x0, s1 = x1;
#pragma unroll
    for (int off = 16; off; off >>= 1) {
        s0 += __shfl_xor_sync(FULL, s0, off);
        s1 += __shfl_xor_sync(FULL, s1, off);
    }
    float m0 = s0 * (1.f / 32.f), m1 = s1 * (1.f / 32.f);
    float d0 = x0 - m0, d1 = x1 - m1;
    float q0 = d0 * d0, q1 = d1 * d1;
#pragma unroll
    for (int off = 16; off; off >>= 1) {
        q0 += __shfl_xor_sync(FULL, q0, off);
        q1 += __shfl_xor_sync(FULL, q1, off);
    }
    float var0 = q0 * (1.f / 32.f), var1 = q1 * (1.f / 32.f);
    float xn0 = d0 * rsqrtf(var0 + GN_EPS) * gnw[lane]      + gnb[lane];
    float xn1 = d1 * rsqrtf(var1 + GN_EPS) * gnw[32 + lane] + gnb[32 + lane];

    // mixing: out[o2] = sum_o xn0(o)*Mw[(2o)*32+o2] + xn1(o)*Mw[(2o+1)*32+o2]
    float acc = 0.f;
#pragma unroll
    for (int o = 0; o < 32; o++) {
        float a0 = __shfl_sync(FULL, xn0, o);
        float a1 = __shfl_sync(FULL, xn1, o);
        acc += a0 * mixW[(o * 2 + 0) * 32 + lane]
             + a1 * mixW[(o * 2 + 1) * 32 + lane];
    }

    // self interaction: sp[o] = b[o] + sum_f feat[a,f] * selfW[o,f]
    const float* frow = feat + a * NF;
    const float* wrow = selfW + lane * NF;
    float sp = selfB[lane];
#pragma unroll
    for (int f = 0; f < NF; f++) sp += frow[f] * wrow[f];

    out[a * NF + lane] = acc + sp;
}

extern "C" void kernel_launch(void* const* d_in, const int* in_sizes, int n_in,
                              void* d_out, int out_size) {
    const float* in_features = (const float*)d_in[0];
    const float* tensor_rhats = (const float*)d_in[1];
    const float* dist_pairs   = (const float*)d_in[2];
    const float* int_weights  = (const float*)d_in[3];
    const float* selfint_w    = (const float*)d_in[4];
    const float* selfint_b    = (const float*)d_in[5];
    const float* mixing_w     = (const float*)d_in[6];
    const float* gn_weight    = (const float*)d_in[7];
    const float* gn_bias      = (const float*)d_in[8];
    const float* sens_mu      = (const float*)d_in[9];
    const float* sens_sigma   = (const float*)d_in[10];
    const int*   pair_first   = (const int*)d_in[11];
    const int*   pair_second  = (const int*)d_in[12];
    float* out = (float*)d_out;

    k0_transpose<<<(S * NF + 255) / 256, 256>>>(int_weights);
    k1_precompute<<<(N_ATOMS * (S / 4) + 255) / 256, 256>>>(in_features);
    {
        int threads = 256;                 // 8 warps/block, 1 warp per atom
        int blocks = (N_ATOMS * 32 + threads - 1) / threads;
        k2_atoms<<<blocks, threads>>>(in_features, tensor_rhats, dist_pairs,
                                      selfint_w, selfint_b, mixing_w,
                                      gn_weight, gn_bias, sens_mu, sens_sigma,
                                      pair_first, pair_second, out);
    }
}

// round 4
// speedup vs baseline: 6.2481x; 1.1050x over previous
#include <cuda_runtime.h>

#define N_ATOMS 8000
#define N_PAIRS 80000
#define NF 32
#define N_DIST 16
#define S (N_DIST * NF)          // 512
#define GN_EPS 1e-5f
#define HARD_CUT 6.5f

// Scratch: A[a][d][o] = sum_f feat[a,f] * W[d,o,f]   (16.4 MB, L2-resident)
__device__ float g_A[N_ATOMS * S];
// Transposed weights: Wt[f][d*32+o] = W[d][o][f]  (64 KB)
__device__ float g_Wt[NF * S];
// Segment starts: pairs for atom a are [g_seg[a], g_seg[a+1])
__device__ int g_seg[N_ATOMS + 1];

// Merged prep: blocks [0,64) transpose W; blocks [64, 64+313) build seg_start.
__global__ void k0_prep(const float* __restrict__ W, const int* __restrict__ pf) {
    int b = blockIdx.x;
    if (b < 64) {
        int idx = b * 256 + threadIdx.x;            // over S*NF = 16384
        int e = idx >> 5;                           // d*32+o
        int f = idx & 31;
        g_Wt[f * S + e] = W[e * NF + f];
    } else {
        int p = (b - 64) * 256 + threadIdx.x;
        if (p >= N_PAIRS) return;
        int cur = pf[p];
        int prev = (p == 0) ? -1 : pf[p - 1];
        for (int x = prev + 1; x <= cur; x++) g_seg[x] = p;
        if (p == N_PAIRS - 1)
            for (int x = cur + 1; x <= N_ATOMS; x++) g_seg[x] = N_PAIRS;
    }
}

// One thread -> 4 consecutive outputs of A[a, :]; fully coalesced float4 loads.
__global__ void __launch_bounds__(256)
k1_precompute(const float* __restrict__ feat) {
    int idx = blockIdx.x * blockDim.x + threadIdx.x;   // over N_ATOMS * 128
    if (idx >= N_ATOMS * (S / 4)) return;
    int a  = idx >> 7;           // 128 float4 per atom
    int e4 = idx & 127;
    const float4* frow4 = reinterpret_cast<const float4*>(feat + a * NF);
    const float4* Wt4   = reinterpret_cast<const float4*>(g_Wt);
    float4 acc = make_float4(0.f, 0.f, 0.f, 0.f);
#pragma unroll
    for (int f4 = 0; f4 < NF / 4; f4++) {
        float4 fr = frow4[f4];
        float4 w0 = Wt4[(4 * f4 + 0) * (S / 4) + e4];
        float4 w1 = Wt4[(4 * f4 + 1) * (S / 4) + e4];
        float4 w2 = Wt4[(4 * f4 + 2) * (S / 4) + e4];
        float4 w3 = Wt4[(4 * f4 + 3) * (S / 4) + e4];
        acc.x += fr.x * w0.x + fr.y * w1.x + fr.z * w2.x + fr.w * w3.x;
        acc.y += fr.x * w0.y + fr.y * w1.y + fr.z * w2.y + fr.w * w3.y;
        acc.z += fr.x * w0.z + fr.y * w1.z + fr.z * w2.z + fr.w * w3.z;
        acc.w += fr.x * w0.w + fr.y * w1.w + fr.z * w2.w + fr.w * w3.w;
    }
    reinterpret_cast<float4*>(g_A)[idx] = acc;
}

__device__ __forceinline__ float sens_lane(float dd, float myMu, float mySig, int lane) {
    float sv = 0.f;
    if (lane < N_DIST) {
        float z   = (1.f / dd - myMu) / mySig;
        float c   = __cosf(dd * (float)(3.14159265358979323846 / (2.0 * 6.5)));
        float cut = (dd < HARD_CUT) ? c * c : 0.f;
        sv = __expf(-0.5f * z * z) * cut;
    }
    return sv;
}

__global__ void __launch_bounds__(128)
k2_atoms(const float* __restrict__ feat,
         const float* __restrict__ rhats,
         const float* __restrict__ dist,
         const float* __restrict__ selfW,
         const float* __restrict__ selfB,
         const float* __restrict__ mixW,
         const float* __restrict__ gnw,
         const float* __restrict__ gnb,
         const float* __restrict__ mu,
         const float* __restrict__ sigma,
         const int* __restrict__ ps,
         float* __restrict__ out) {
    const unsigned FULL = 0xffffffffu;
    int warp = (blockIdx.x * blockDim.x + threadIdx.x) >> 5;
    int lane = threadIdx.x & 31;
    if (warp >= N_ATOMS) return;
    const int a = warp;

    const int segs = g_seg[a];
    const int sege = g_seg[a + 1];

    float myMu = 0.f, mySig = 1.f;
    if (lane < N_DIST) { myMu = mu[lane]; mySig = sigma[lane]; }

    float tf0 = 0.f, tf1 = 0.f, tf2 = 0.f, tf3 = 0.f;

    int p = segs;
    // unroll-2: 32 gather loads in flight per iteration
    for (; p + 2 <= sege; p += 2) {
        int   j0  = ps[p],     j1  = ps[p + 1];
        float dd0 = dist[p],   dd1 = dist[p + 1];
        float4 r0 = *reinterpret_cast<const float4*>(rhats + 4 * p);
        float4 r1 = *reinterpret_cast<const float4*>(rhats + 4 * (p + 1));

        float sv0 = sens_lane(dd0, myMu, mySig, lane);
        float sv1 = sens_lane(dd1, myMu, mySig, lane);

        const float* A0 = g_A + j0 * S;
        const float* A1 = g_A + j1 * S;
        float av0[N_DIST], av1[N_DIST];
#pragma unroll
        for (int d = 0; d < N_DIST; d++) av0[d] = A0[d * NF + lane];
#pragma unroll
        for (int d = 0; d < N_DIST; d++) av1[d] = A1[d * NF + lane];

        float v0 = 0.f, v1 = 0.f;
#pragma unroll
        for (int d = 0; d < N_DIST; d++) {
            v0 += __shfl_sync(FULL, sv0, d) * av0[d];
            v1 += __shfl_sync(FULL, sv1, d) * av1[d];
        }
        tf0 += r0.x * v0 + r1.x * v1;
        tf1 += r0.y * v0 + r1.y * v1;
        tf2 += r0.z * v0 + r1.z * v1;
        tf3 += r0.w * v0 + r1.w * v1;
    }
    if (p < sege) {
        int   j  = ps[p];
        float dd = dist[p];
        float4 r = *reinterpret_cast<const float4*>(rhats + 4 * p);
        float sv = sens_lane(dd, myMu, mySig, lane);
        const float* Aj = g_A + j * S;
        float av[N_DIST];
#pragma unroll
        for (int d = 0; d < N_DIST; d++) av[d] = Aj[d * NF + lane];
        float v = 0.f;
#pragma unroll
        for (int d = 0; d < N_DIST; d++)
            v += __shfl_sync(FULL, sv, d) * av[d];
        tf0 += r.x * v; tf1 += r.y * v; tf2 += r.z * v; tf3 += r.w * v;
    }

    // invariants: x0 = l=0 scalar, x1 = |l=1 vector|^2
    float x0 = tf0;
    float x1 = tf1 * tf1 + tf2 * tf2 + tf3 * tf3;

    // GroupNorm: each group == the 32 lanes of this warp
    float s0 = x0, s1 = x1;
#pragma unroll
    for (int off = 16; off; off >>= 1) {
        s0 += __shfl_xor_sync(FULL, s0, off);
        s1 += __shfl_xor_sync(FULL, s1, off);
    }
    float m0 = s0 * (1.f / 32.f), m1 = s1 * (1.f / 32.f);
    float d0 = x0 - m0, d1 = x1 - m1;
    float q0 = d0 * d0, q1 = d1 * d1;
#pragma unroll
    for (int off = 16; off; off >>= 1) {
        q0 += __shfl_xor_sync(FULL, q0, off);
        q1 += __shfl_xor_sync(FULL, q1, off);
    }
    float var0 = q0 * (1.f / 32.f), var1 = q1 * (1.f / 32.f);
    float xn0 = d0 * rsqrtf(var0 + GN_EPS) * gnw[lane]      + gnb[lane];
    float xn1 = d1 * rsqrtf(var1 + GN_EPS) * gnw[32 + lane] + gnb[32 + lane];

    // mixing: out[o2] = sum_o xn0(o)*Mw[(2o)*32+o2] + xn1(o)*Mw[(2o+1)*32+o2]
    float acc = 0.f;
#pragma unroll
    for (int o = 0; o < 32; o++) {
        float a0 = __shfl_sync(FULL, xn0, o);
        float a1 = __shfl_sync(FULL, xn1, o);
        acc += a0 * mixW[(o * 2 + 0) * 32 + lane]
             + a1 * mixW[(o * 2 + 1) * 32 + lane];
    }

    // self interaction: sp[o] = b[o] + sum_f feat[a,f] * selfW[o,f]
    const float* frow = feat + a * NF;
    const float* wrow = selfW + lane * NF;
    float sp = selfB[lane];
#pragma unroll
    for (int f = 0; f < NF; f++) sp += frow[f] * wrow[f];

    out[a * NF + lane] = acc + sp;
}

extern "C" void kernel_launch(void* const* d_in, const int* in_sizes, int n_in,
                              void* d_out, int out_size) {
    const float* in_features = (const float*)d_in[0];
    const float* tensor_rhats = (const float*)d_in[1];
    const float* dist_pairs   = (const float*)d_in[2];
    const float* int_weights  = (const float*)d_in[3];
    const float* selfint_w    = (const float*)d_in[4];
    const float* selfint_b    = (const float*)d_in[5];
    const float* mixing_w     = (const float*)d_in[6];
    const float* gn_weight    = (const float*)d_in[7];
    const float* gn_bias      = (const float*)d_in[8];
    const float* sens_mu      = (const float*)d_in[9];
    const float* sens_sigma   = (const float*)d_in[10];
    const int*   pair_first   = (const int*)d_in[11];
    const int*   pair_second  = (const int*)d_in[12];
    float* out = (float*)d_out;

    // 64 transpose blocks + ceil(80000/256)=313 seg blocks
    k0_prep<<<64 + (N_PAIRS + 255) / 256, 256>>>(int_weights, pair_first);
    k1_precompute<<<(N_ATOMS * (S / 4) + 255) / 256, 256>>>(in_features);
    {
        int threads = 128;                 // 4 warps/block, 1 warp per atom
        int blocks = (N_ATOMS * 32 + threads - 1) / threads;
        k2_atoms<<<blocks, threads>>>(in_features, tensor_rhats, dist_pairs,
                                      selfint_w, selfint_b, mixing_w,
                                      gn_weight, gn_bias, sens_mu, sens_sigma,
                                      pair_second, out);
    }
}

// round 5
// speedup vs baseline: 7.1237x; 1.1401x over previous
#include <cuda_runtime.h>
#include <cuda_fp16.h>

#define N_ATOMS 8000
#define N_PAIRS 80000
#define NF 32
#define N_DIST 16
#define S (N_DIST * NF)          // 512
#define GN_EPS 1e-5f
#define HARD_CUT 6.5f

// A[a][o][d] in fp16: 8.2 MB, deeply L2-resident
__device__ __half g_Ah[N_ATOMS * S];
// Transposed weights: Wt2[f][o*16+d] = W[d][o][f]  (64 KB fp32)
__device__ float g_Wt2[NF * S];
// Precomputed sensitivities sense[p][d]  (5 MB)
__device__ float g_sense[N_PAIRS * N_DIST];
// Segment starts: pairs for atom a are [g_seg[a], g_seg[a+1])
__device__ int g_seg[N_ATOMS + 1];

// Merged prep:
//  blocks [0,64): transpose W -> Wt2
//  blocks [64, 64+313): build seg_start from sorted pair_first
//  blocks [377, 377+313): per-pair sensitivities
__global__ void k0_prep(const float* __restrict__ W, const int* __restrict__ pf,
                        const float* __restrict__ dist,
                        const float* __restrict__ mu, const float* __restrict__ sigma) {
    int b = blockIdx.x;
    if (b < 64) {
        int idx = b * 256 + threadIdx.x;            // over S*NF = 16384
        int d = idx & 15;
        int o = (idx >> 4) & 31;
        int f = idx >> 9;
        g_Wt2[idx] = W[(d * NF + o) * NF + f];
    } else if (b < 64 + 313) {
        int p = (b - 64) * 256 + threadIdx.x;
        if (p >= N_PAIRS) return;
        int cur = pf[p];
        int prev = (p == 0) ? -1 : pf[p - 1];
        for (int x = prev + 1; x <= cur; x++) g_seg[x] = p;
        if (p == N_PAIRS - 1)
            for (int x = cur + 1; x <= N_ATOMS; x++) g_seg[x] = N_PAIRS;
    } else {
        int p = (b - 377) * 256 + threadIdx.x;
        if (p >= N_PAIRS) return;
        float dd  = dist[p];
        float inv = 1.f / dd;
        float c   = __cosf(dd * (float)(3.14159265358979323846 / (2.0 * 6.5)));
        float cut = (dd < HARD_CUT) ? c * c : 0.f;
        float4* outp = reinterpret_cast<float4*>(g_sense + p * N_DIST);
#pragma unroll
        for (int q = 0; q < 4; q++) {
            float4 r;
            float z0 = (inv - mu[4 * q + 0]) / sigma[4 * q + 0];
            float z1 = (inv - mu[4 * q + 1]) / sigma[4 * q + 1];
            float z2 = (inv - mu[4 * q + 2]) / sigma[4 * q + 2];
            float z3 = (inv - mu[4 * q + 3]) / sigma[4 * q + 3];
            r.x = __expf(-0.5f * z0 * z0) * cut;
            r.y = __expf(-0.5f * z1 * z1) * cut;
            r.z = __expf(-0.5f * z2 * z2) * cut;
            r.w = __expf(-0.5f * z3 * z3) * cut;
            outp[q] = r;
        }
    }
}

// k1: A[a][o][d] = sum_f feat[a,f] * W[d,o,f], 4 atoms per thread to amortize Wt.
// Thread (group g, e4): e4 = o*4 + dq covers d = 4*dq .. 4*dq+3 of output channel o.
__global__ void __launch_bounds__(256)
k1_precompute(const float* __restrict__ feat) {
    int idx = blockIdx.x * blockDim.x + threadIdx.x;   // over (N_ATOMS/4)*128
    if (idx >= (N_ATOMS / 4) * 128) return;
    int a0 = (idx >> 7) * 4;
    int e4 = idx & 127;
    const float4* feat4 = reinterpret_cast<const float4*>(feat);
    const float4* Wt4   = reinterpret_cast<const float4*>(g_Wt2);
    float4 acc0 = make_float4(0.f, 0.f, 0.f, 0.f);
    float4 acc1 = acc0, acc2 = acc0, acc3 = acc0;
#pragma unroll
    for (int f4 = 0; f4 < 8; f4++) {
        float4 w0 = Wt4[(4 * f4 + 0) * 128 + e4];
        float4 w1 = Wt4[(4 * f4 + 1) * 128 + e4];
        float4 w2 = Wt4[(4 * f4 + 2) * 128 + e4];
        float4 w3 = Wt4[(4 * f4 + 3) * 128 + e4];
        float4 fr0 = feat4[(a0 + 0) * 8 + f4];
        float4 fr1 = feat4[(a0 + 1) * 8 + f4];
        float4 fr2 = feat4[(a0 + 2) * 8 + f4];
        float4 fr3 = feat4[(a0 + 3) * 8 + f4];
        acc0.x += fr0.x * w0.x + fr0.y * w1.x + fr0.z * w2.x + fr0.w * w3.x;
        acc0.y += fr0.x * w0.y + fr0.y * w1.y + fr0.z * w2.y + fr0.w * w3.y;
        acc0.z += fr0.x * w0.z + fr0.y * w1.z + fr0.z * w2.z + fr0.w * w3.z;
        acc0.w += fr0.x * w0.w + fr0.y * w1.w + fr0.z * w2.w + fr0.w * w3.w;
        acc1.x += fr1.x * w0.x + fr1.y * w1.x + fr1.z * w2.x + fr1.w * w3.x;
        acc1.y += fr1.x * w0.y + fr1.y * w1.y + fr1.z * w2.y + fr1.w * w3.y;
        acc1.z += fr1.x * w0.z + fr1.y * w1.z + fr1.z * w2.z + fr1.w * w3.z;
        acc1.w += fr1.x * w0.w + fr1.y * w1.w + fr1.z * w2.w + fr1.w * w3.w;
        acc2.x += fr2.x * w0.x + fr2.y * w1.x + fr2.z * w2.x + fr2.w * w3.x;
        acc2.y += fr2.x * w0.y + fr2.y * w1.y + fr2.z * w2.y + fr2.w * w3.y;
        acc2.z += fr2.x * w0.z + fr2.y * w1.z + fr2.z * w2.z + fr2.w * w3.z;
        acc2.w += fr2.x * w0.w + fr2.y * w1.w + fr2.z * w2.w + fr2.w * w3.w;
        acc3.x += fr3.x * w0.x + fr3.y * w1.x + fr3.z * w2.x + fr3.w * w3.x;
        acc3.y += fr3.x * w0.y + fr3.y * w1.y + fr3.z * w2.y + fr3.w * w3.y;
        acc3.z += fr3.x * w0.z + fr3.y * w1.z + fr3.z * w2.z + fr3.w * w3.z;
        acc3.w += fr3.x * w0.w + fr3.y * w1.w + fr3.z * w2.w + fr3.w * w3.w;
    }
    __half2* o0 = reinterpret_cast<__half2*>(g_Ah + (a0 + 0) * S + e4 * 4);
    __half2* o1 = reinterpret_cast<__half2*>(g_Ah + (a0 + 1) * S + e4 * 4);
    __half2* o2 = reinterpret_cast<__half2*>(g_Ah + (a0 + 2) * S + e4 * 4);
    __half2* o3 = reinterpret_cast<__half2*>(g_Ah + (a0 + 3) * S + e4 * 4);
    o0[0] = __floats2half2_rn(acc0.x, acc0.y); o0[1] = __floats2half2_rn(acc0.z, acc0.w);
    o1[0] = __floats2half2_rn(acc1.x, acc1.y); o1[1] = __floats2half2_rn(acc1.z, acc1.w);
    o2[0] = __floats2half2_rn(acc2.x, acc2.y); o2[1] = __floats2half2_rn(acc2.z, acc2.w);
    o3[0] = __floats2half2_rn(acc3.x, acc3.y); o3[1] = __floats2half2_rn(acc3.z, acc3.w);
}

// Per-pair body: lane = output channel o; 2 LDG.128 of halves + 4 uniform float4.
__device__ __forceinline__ void pair_body(int p, int lane, const int* __restrict__ ps,
                                          const float* __restrict__ rhats,
                                          float& tf0, float& tf1, float& tf2, float& tf3) {
    int j = ps[p];
    float4 r = *reinterpret_cast<const float4*>(rhats + 4 * p);
    const float4* Ap = reinterpret_cast<const float4*>(g_Ah + j * S + lane * N_DIST);
    float4 ha = Ap[0];          // halves d0..d7
    float4 hb = Ap[1];          // halves d8..d15
    const float4* sp = reinterpret_cast<const float4*>(g_sense + p * N_DIST);
    float4 s0 = sp[0], s1 = sp[1], s2 = sp[2], s3 = sp[3];

    const __half2* h = reinterpret_cast<const __half2*>(&ha);
    float2 f0 = __half22float2(h[0]);
    float2 f1 = __half22float2(h[1]);
    float2 f2 = __half22float2(h[2]);
    float2 f3 = __half22float2(h[3]);
    const __half2* g = reinterpret_cast<const __half2*>(&hb);
    float2 f4 = __half22float2(g[0]);
    float2 f5 = __half22float2(g[1]);
    float2 f6 = __half22float2(g[2]);
    float2 f7 = __half22float2(g[3]);

    float v = s0.x * f0.x + s0.y * f0.y + s0.z * f1.x + s0.w * f1.y
            + s1.x * f2.x + s1.y * f2.y + s1.z * f3.x + s1.w * f3.y
            + s2.x * f4.x + s2.y * f4.y + s2.z * f5.x + s2.w * f5.y
            + s3.x * f6.x + s3.y * f6.y + s3.z * f7.x + s3.w * f7.y;

    tf0 += r.x * v; tf1 += r.y * v; tf2 += r.z * v; tf3 += r.w * v;
}

__global__ void __launch_bounds__(128)
k2_atoms(const float* __restrict__ feat,
         const float* __restrict__ rhats,
         const float* __restrict__ selfW,
         const float* __restrict__ selfB,
         const float* __restrict__ mixW,
         const float* __restrict__ gnw,
         const float* __restrict__ gnb,
         const int* __restrict__ ps,
         float* __restrict__ out) {
    const unsigned FULL = 0xffffffffu;
    int warp = (blockIdx.x * blockDim.x + threadIdx.x) >> 5;
    int lane = threadIdx.x & 31;
    if (warp >= N_ATOMS) return;
    const int a = warp;

    const int segs = g_seg[a];
    const int sege = g_seg[a + 1];

    float tf0 = 0.f, tf1 = 0.f, tf2 = 0.f, tf3 = 0.f;
    float u0 = 0.f, u1 = 0.f, u2 = 0.f, u3 = 0.f;

    int p = segs;
    for (; p + 2 <= sege; p += 2) {
        pair_body(p,     lane, ps, rhats, tf0, tf1, tf2, tf3);
        pair_body(p + 1, lane, ps, rhats, u0, u1, u2, u3);
    }
    if (p < sege) pair_body(p, lane, ps, rhats, tf0, tf1, tf2, tf3);
    tf0 += u0; tf1 += u1; tf2 += u2; tf3 += u3;

    // invariants: x0 = l=0 scalar, x1 = |l=1 vector|^2
    float x0 = tf0;
    float x1 = tf1 * tf1 + tf2 * tf2 + tf3 * tf3;

    // GroupNorm: each group == the 32 lanes of this warp
    float s0 = x0, s1 = x1;
#pragma unroll
    for (int off = 16; off; off >>= 1) {
        s0 += __shfl_xor_sync(FULL, s0, off);
        s1 += __shfl_xor_sync(FULL, s1, off);
    }
    float m0 = s0 * (1.f / 32.f), m1 = s1 * (1.f / 32.f);
    float d0 = x0 - m0, d1 = x1 - m1;
    float q0 = d0 * d0, q1 = d1 * d1;
#pragma unroll
    for (int off = 16; off; off >>= 1) {
        q0 += __shfl_xor_sync(FULL, q0, off);
        q1 += __shfl_xor_sync(FULL, q1, off);
    }
    float var0 = q0 * (1.f / 32.f), var1 = q1 * (1.f / 32.f);
    float xn0 = d0 * rsqrtf(var0 + GN_EPS) * gnw[lane]      + gnb[lane];
    float xn1 = d1 * rsqrtf(var1 + GN_EPS) * gnw[32 + lane] + gnb[32 + lane];

    // mixing: out[o2] = sum_o xn0(o)*Mw[(2o)*32+o2] + xn1(o)*Mw[(2o+1)*32+o2]
    float acc = 0.f;
#pragma unroll
    for (int o = 0; o < 32; o++) {
        float a0 = __shfl_sync(FULL, xn0, o);
        float a1 = __shfl_sync(FULL, xn1, o);
        acc += a0 * mixW[(o * 2 + 0) * 32 + lane]
             + a1 * mixW[(o * 2 + 1) * 32 + lane];
    }

    // self interaction: sp[o] = b[o] + sum_f feat[a,f] * selfW[o,f]
    const float* frow = feat + a * NF;
    const float* wrow = selfW + lane * NF;
    float sp = selfB[lane];
#pragma unroll
    for (int f = 0; f < NF; f++) sp += frow[f] * wrow[f];

    out[a * NF + lane] = acc + sp;
}

extern "C" void kernel_launch(void* const* d_in, const int* in_sizes, int n_in,
                              void* d_out, int out_size) {
    const float* in_features = (const float*)d_in[0];
    const float* tensor_rhats = (const float*)d_in[1];
    const float* dist_pairs   = (const float*)d_in[2];
    const float* int_weights  = (const float*)d_in[3];
    const float* selfint_w    = (const float*)d_in[4];
    const float* selfint_b    = (const float*)d_in[5];
    const float* mixing_w     = (const float*)d_in[6];
    const float* gn_weight    = (const float*)d_in[7];
    const float* gn_bias      = (const float*)d_in[8];
    const float* sens_mu      = (const float*)d_in[9];
    const float* sens_sigma   = (const float*)d_in[10];
    const int*   pair_first   = (const int*)d_in[11];
    const int*   pair_second  = (const int*)d_in[12];
    float* out = (float*)d_out;

    // 64 transpose + 313 seg + 313 sense blocks
    k0_prep<<<64 + 2 * ((N_PAIRS + 255) / 256), 256>>>(int_weights, pair_first,
                                                       dist_pairs, sens_mu, sens_sigma);
    k1_precompute<<<((N_ATOMS / 4) * 128 + 255) / 256, 256>>>(in_features);
    {
        int threads = 128;                 // 4 warps/block, 1 warp per atom
        int blocks = (N_ATOMS * 32 + threads - 1) / threads;
        k2_atoms<<<blocks, threads>>>(in_features, tensor_rhats,
                                      selfint_w, selfint_b, mixing_w,
                                      gn_weight, gn_bias, pair_second, out);
    }
}